// round 6
// baseline (speedup 1.0000x reference)
#include <cuda_runtime.h>
#include <cuda_fp16.h>
#include <cstdint>

// AntisymmetricLayer via fp16 mma.sync.m16n8k16 (fp32 accum).
//   z = x1-x2, s = x1+x2 (fp16 rn)
//   Phase L: lin = z @ W^T -> out (dense)
//   Main: zP = z @ P^T, sQ = s @ Q^T per 4-k group; epilogue RMW: out += sum_r zP*sQ
// CTA: 64 tokens, 4 warps (2M x 2N), 96KB smem, launch_bounds(128,2) -> 255 regs, no spills.
// B slabs double-buffered via cp.async; 2 CTAs/SM, warps of different CTAs share each SMSP.

#define D128 128
#define KTOT 64
#define MTILE 64
#define NGRP 16
#define THREADS 128

// smem byte offsets (rows of 256B = 128 halfs, 16B chunks XOR-swizzled by row&7)
#define ZSH 0
#define SSH 16384
#define BBASE 32768          // buf b: P at BBASE + b*32768, Q at +16384
#define SMEM_BYTES 98304     // 96KB

__device__ __align__(16) __half g_Pt[KTOT * 16 * D128];
__device__ __align__(16) __half g_Qt[KTOT * 16 * D128];

__device__ __forceinline__ uint32_t smem_u32(const void* p) {
    uint32_t a;
    asm("{ .reg .u64 t; cvta.to.shared.u64 t, %1; cvt.u32.u64 %0, t; }" : "=r"(a) : "l"(p));
    return a;
}

#define LDSM_X4(r0, r1, r2, r3, a) \
    asm volatile("ldmatrix.sync.aligned.m8n8.x4.shared.b16 {%0,%1,%2,%3}, [%4];" \
        : "=r"(r0), "=r"(r1), "=r"(r2), "=r"(r3) : "r"(a))

#define CP_ASYNC16(dst, src) \
    asm volatile("cp.async.cg.shared.global [%0], [%1], 16;" :: "r"(dst), "l"(src))
#define CP_COMMIT() asm volatile("cp.async.commit_group;" ::: "memory")
#define CP_WAIT(N)  asm volatile("cp.async.wait_group %0;" :: "n"(N) : "memory")

__device__ __forceinline__ void mma_f16(float* d, const uint32_t* a, const uint32_t* b) {
    asm volatile("mma.sync.aligned.m16n8k16.row.col.f32.f16.f16.f32 "
                 "{%0,%1,%2,%3}, {%4,%5,%6,%7}, {%8,%9}, {%0,%1,%2,%3};"
                 : "+f"(d[0]), "+f"(d[1]), "+f"(d[2]), "+f"(d[3])
                 : "r"(a[0]), "r"(a[1]), "r"(a[2]), "r"(a[3]),
                   "r"(b[0]), "r"(b[1]));
}

// ---------------- pre-transpose P,Q -> [(k,r)][d] fp16 ----------------
__global__ void transpose_pq(const float* __restrict__ P, const float* __restrict__ Q) {
    int i = blockIdx.x * 256 + threadIdx.x;   // i = (k*128+d)*16 + r
    int r = i & 15, d = (i >> 4) & 127, k = i >> 11;
    int o = (k * 16 + r) * 128 + d;
    g_Pt[o] = __float2half_rn(P[i]);
    g_Qt[o] = __float2half_rn(Q[i]);
}

// issue cp.async for group g's P,Q slabs into buffer b
__device__ __forceinline__ void stage_pq(uint32_t smb, int g, int b, int tid) {
    const char* gp = reinterpret_cast<const char*>(g_Pt);
    const char* gq = reinterpret_cast<const char*>(g_Qt);
    const uint32_t base = smb + BBASE + (uint32_t)b * 32768;
    #pragma unroll
    for (int it = 0; it < 8; it++) {
        int lin = it * THREADS + tid;     // 0..1023
        int n = lin >> 4, c = lin & 15;   // col, 16B-chunk
        uint32_t so = base + (uint32_t)(n * 256 + ((c ^ (n & 7)) << 4));
        int64_t go = ((int64_t)(g * 64 + n) * 128 + c * 8) * 2;
        CP_ASYNC16(so, gp + go);
        CP_ASYNC16(so + 16384, gq + go);
    }
}

// ---------------- main kernel ----------------
__global__ __launch_bounds__(THREADS, 2)
void antisym_h(const float* __restrict__ x1, const float* __restrict__ x2,
               const float* __restrict__ W, float* __restrict__ out)
{
    extern __shared__ char shm[];
    const uint32_t smb = smem_u32(shm);
    const int tid = threadIdx.x;
    const int lane = tid & 31;
    const int wid = tid >> 5;
    const int wm = wid & 1;        // M-warp 0..1
    const int wn = wid >> 1;       // N-warp 0..1
    const int g4 = lane >> 2;
    const int c4 = lane & 3;
    const int mbase = blockIdx.x * MTILE;

    // ---- stage z,s as fp16 (swizzled) + W into buf0 P region ----
    {
        const float4* x1v = reinterpret_cast<const float4*>(x1) + (size_t)mbase * 32;
        const float4* x2v = reinterpret_cast<const float4*>(x2) + (size_t)mbase * 32;
        #pragma unroll
        for (int it = 0; it < 8; it++) {
            int idx = it * THREADS + tid;            // 1024 chunks
            int m = idx >> 4, c = idx & 15;
            float4 a0 = x1v[m * 32 + c * 2];
            float4 a1 = x1v[m * 32 + c * 2 + 1];
            float4 b0 = x2v[m * 32 + c * 2];
            float4 b1 = x2v[m * 32 + c * 2 + 1];
            half2 zz[4], ss[4];
            zz[0] = __floats2half2_rn(a0.x - b0.x, a0.y - b0.y);
            zz[1] = __floats2half2_rn(a0.z - b0.z, a0.w - b0.w);
            zz[2] = __floats2half2_rn(a1.x - b1.x, a1.y - b1.y);
            zz[3] = __floats2half2_rn(a1.z - b1.z, a1.w - b1.w);
            ss[0] = __floats2half2_rn(a0.x + b0.x, a0.y + b0.y);
            ss[1] = __floats2half2_rn(a0.z + b0.z, a0.w + b0.w);
            ss[2] = __floats2half2_rn(a1.x + b1.x, a1.y + b1.y);
            ss[3] = __floats2half2_rn(a1.z + b1.z, a1.w + b1.w);
            uint32_t so = (uint32_t)(m * 256 + ((c ^ (m & 7)) << 4));
            *reinterpret_cast<uint4*>(shm + ZSH + so) = *reinterpret_cast<uint4*>(zz);
            *reinterpret_cast<uint4*>(shm + SSH + so) = *reinterpret_cast<uint4*>(ss);
        }
        // W (64 rows x 128 halfs) into buf0 P region, swizzled
        #pragma unroll
        for (int it = 0; it < 8; it++) {
            int idx = it * THREADS + tid;            // 1024 chunks
            int r = idx >> 4, c = idx & 15;
            float4 w0 = reinterpret_cast<const float4*>(W)[r * 32 + c * 2];
            float4 w1 = reinterpret_cast<const float4*>(W)[r * 32 + c * 2 + 1];
            half2 ww[4];
            ww[0] = __floats2half2_rn(w0.x, w0.y);
            ww[1] = __floats2half2_rn(w0.z, w0.w);
            ww[2] = __floats2half2_rn(w1.x, w1.y);
            ww[3] = __floats2half2_rn(w1.z, w1.w);
            uint32_t so = (uint32_t)(r * 256 + ((c ^ (r & 7)) << 4));
            *reinterpret_cast<uint4*>(shm + BBASE + so) = *reinterpret_cast<uint4*>(ww);
        }
    }
    __syncthreads();

    // ---- per-lane fragment row bases ----
    const int xr = lane & 7;
    uint32_t rowA[2];
    #pragma unroll
    for (int i = 0; i < 2; i++)
        rowA[i] = (uint32_t)((wm * 32 + i * 16 + ((lane >> 3) & 1) * 8 + xr) * 256);
    const int krelA = lane >> 4;
    const int krelB = (lane >> 3) & 1;
    // main-loop B rows: lanes<16 read P, lanes>=16 read Q (buffer offset added later)
    const uint32_t bsel = (lane < 16) ? 0u : 16384u;
    uint32_t rowB[4];
    #pragma unroll
    for (int j = 0; j < 4; j++)
        rowB[j] = smb + BBASE + bsel + (uint32_t)((wn * 32 + j * 8 + xr) * 256);

    // ---- Phase L: lin = z @ W^T (dense), store to out ----
    {
        uint32_t rowW[2];
        #pragma unroll
        for (int j2 = 0; j2 < 2; j2++)
            rowW[j2] = smb + BBASE +
                (uint32_t)(((wn * 4 + j2 * 2 + (lane >> 4)) * 8 + xr) * 256);

        float lw[2][4][4] = {};
        #pragma unroll
        for (int ks = 0; ks < 8; ks++) {
            uint32_t offA = (uint32_t)(((2 * ks + krelA) ^ xr) << 4);
            uint32_t offB = (uint32_t)(((2 * ks + krelB) ^ xr) << 4);
            uint32_t az[2][4];
            #pragma unroll
            for (int i = 0; i < 2; i++)
                LDSM_X4(az[i][0], az[i][1], az[i][2], az[i][3],
                        smb + ZSH + rowA[i] + offA);
            #pragma unroll
            for (int j2 = 0; j2 < 2; j2++) {
                uint32_t r0, r1, r2, r3;
                LDSM_X4(r0, r1, r2, r3, rowW[j2] + offB);
                uint32_t ba[2] = {r0, r1}, bb[2] = {r2, r3};
                #pragma unroll
                for (int i = 0; i < 2; i++) {
                    mma_f16(lw[i][j2 * 2],     az[i], ba);
                    mma_f16(lw[i][j2 * 2 + 1], az[i], bb);
                }
            }
        }
        #pragma unroll
        for (int i = 0; i < 2; i++) {
            int m0 = mbase + wm * 32 + i * 16 + g4;
            #pragma unroll
            for (int t = 0; t < 4; t++) {
                int k0 = wn * 32 + t * 8 + 2 * c4;
                *reinterpret_cast<float2*>(&out[(size_t)m0 * KTOT + k0]) =
                    make_float2(lw[i][t][0], lw[i][t][1]);
                *reinterpret_cast<float2*>(&out[(size_t)(m0 + 8) * KTOT + k0]) =
                    make_float2(lw[i][t][2], lw[i][t][3]);
            }
        }
    }
    __syncthreads();   // W reads done -> buf0 reusable; lin visible CTA-wide

    // ---- prologue: stage group 0 into buf0 ----
    stage_pq(smb, 0, 0, tid);
    CP_COMMIT();

    // ---- group loop ----
    for (int g = 0; g < NGRP; g++) {
        // stage next group into the other buffer, then wait for current
        if (g + 1 < NGRP) {
            stage_pq(smb, g + 1, (g + 1) & 1, tid);
            CP_COMMIT();
            CP_WAIT(1);
        } else {
            CP_WAIT(0);
        }
        __syncthreads();                   // current slab visible to all warps

        const uint32_t bufoff = (uint32_t)(g & 1) * 32768;

        float zp[2][4][4] = {};
        float sq[2][4][4] = {};

        #pragma unroll
        for (int ks = 0; ks < 8; ks++) {
            uint32_t offA = (uint32_t)(((2 * ks + krelA) ^ xr) << 4);
            uint32_t offB = (uint32_t)(((2 * ks + krelB) ^ xr) << 4) + bufoff;
            uint32_t az[2][4], as_[2][4];
            #pragma unroll
            for (int i = 0; i < 2; i++) {
                LDSM_X4(az[i][0], az[i][1], az[i][2], az[i][3],
                        smb + ZSH + rowA[i] + offA);
                LDSM_X4(as_[i][0], as_[i][1], as_[i][2], as_[i][3],
                        smb + SSH + rowA[i] + offA);
            }
            #pragma unroll
            for (int j = 0; j < 4; j++) {
                uint32_t r0, r1, r2, r3;
                LDSM_X4(r0, r1, r2, r3, rowB[j] + offB);
                uint32_t bp[2] = {r0, r1}, bq[2] = {r2, r3};
                #pragma unroll
                for (int i = 0; i < 2; i++) {
                    mma_f16(zp[i][j], az[i], bp);
                    mma_f16(sq[i][j], as_[i], bq);
                }
            }
        }
        __syncthreads();                   // slab consumed; restage-safe next iter

        // ---- epilogue: reduce r, RMW out (overlaps next group's cp.async) ----
        const int kA = g * 4 + wn * 2;
        const int mr0 = mbase + wm * 32 + g4;
        #pragma unroll
        for (int i = 0; i < 2; i++) {
            float pa0 = zp[i][0][0]*sq[i][0][0] + zp[i][0][1]*sq[i][0][1]
                      + zp[i][1][0]*sq[i][1][0] + zp[i][1][1]*sq[i][1][1];
            float pa1 = zp[i][0][2]*sq[i][0][2] + zp[i][0][3]*sq[i][0][3]
                      + zp[i][1][2]*sq[i][1][2] + zp[i][1][3]*sq[i][1][3];
            float pb0 = zp[i][2][0]*sq[i][2][0] + zp[i][2][1]*sq[i][2][1]
                      + zp[i][3][0]*sq[i][3][0] + zp[i][3][1]*sq[i][3][1];
            float pb1 = zp[i][2][2]*sq[i][2][2] + zp[i][2][3]*sq[i][2][3]
                      + zp[i][3][2]*sq[i][3][2] + zp[i][3][3]*sq[i][3][3];
            pa0 += __shfl_xor_sync(~0u, pa0, 1); pa0 += __shfl_xor_sync(~0u, pa0, 2);
            pa1 += __shfl_xor_sync(~0u, pa1, 1); pa1 += __shfl_xor_sync(~0u, pa1, 2);
            pb0 += __shfl_xor_sync(~0u, pb0, 1); pb0 += __shfl_xor_sync(~0u, pb0, 2);
            pb1 += __shfl_xor_sync(~0u, pb1, 1); pb1 += __shfl_xor_sync(~0u, pb1, 2);
            if (c4 == wn) {
                int m0 = mr0 + i * 16;
                float2 l0 = *reinterpret_cast<const float2*>(&out[(size_t)m0 * KTOT + kA]);
                float2 l1 = *reinterpret_cast<const float2*>(&out[(size_t)(m0 + 8) * KTOT + kA]);
                *reinterpret_cast<float2*>(&out[(size_t)m0 * KTOT + kA]) =
                    make_float2(l0.x + pa0, l0.y + pb0);
                *reinterpret_cast<float2*>(&out[(size_t)(m0 + 8) * KTOT + kA]) =
                    make_float2(l1.x + pa1, l1.y + pb1);
            }
        }
    }
}

extern "C" void kernel_launch(void* const* d_in, const int* in_sizes, int n_in,
                              void* d_out, int out_size)
{
    const float* x1 = (const float*)d_in[0];
    const float* x2 = (const float*)d_in[1];
    const float* W  = (const float*)d_in[2];
    const float* P  = (const float*)d_in[3];
    const float* Q  = (const float*)d_in[4];
    float* out = (float*)d_out;

    transpose_pq<<<512, 256>>>(P, Q);

    const int tokens = in_sizes[0] / D128;
    const int blocks = tokens / MTILE;      // 2048

    cudaFuncSetAttribute(antisym_h,
                         cudaFuncAttributeMaxDynamicSharedMemorySize, SMEM_BYTES);
    antisym_h<<<blocks, THREADS, SMEM_BYTES>>>(x1, x2, W, out);
}

// round 7
// speedup vs baseline: 1.1885x; 1.1885x over previous
#include <cuda_runtime.h>
#include <cuda_fp16.h>
#include <cstdint>

// AntisymmetricLayer via fp16 mma.sync.m16n8k16 (fp32 accum).
//   z = x1-x2, s = x1+x2 (fp16)
//   Phase L: lin = z @ W^T -> out (W fragment-packed per warp so ownership matches epilogue)
//   Main: per 4-k group, zP = z @ P^T, sQ = s @ Q^T; epilogue RMW out += sum_r zP*sQ
// Key change vs r6: NO B staging. P,Q are pre-packed into MMA-fragment order in a
// one-time kernel; the main loop loads B fragments with one LDG.128 per tile from L2
// (524KB, L2-resident). No cp.async, no B smem, no main-loop __syncthreads.
// CTA: 128 tokens, 4 warps (2M x 2N), warp tile 64x32, 64KB smem -> 2 CTAs/SM.

#define D128 128
#define KTOT 64
#define MTILE 128
#define NGRP 16
#define THREADS 128

#define ZSH 0
#define SSH 32768
#define SMEM_BYTES 65536

// fragment-packed B: [g][ks][wn][j] blocks of 512B (32 lanes x 16B = P.b0,b1,Q.b0,b1)
__device__ __align__(16) __half g_B[16 * 8 * 2 * 4 * 256];
// fragment-packed W: [ks][wn][t] blocks of 256B (32 lanes x 8B)
__device__ __align__(16) __half g_Wt[8 * 2 * 4 * 128];

__device__ __forceinline__ uint32_t smem_u32(const void* p) {
    uint32_t a;
    asm("{ .reg .u64 t; cvta.to.shared.u64 t, %1; cvt.u32.u64 %0, t; }" : "=r"(a) : "l"(p));
    return a;
}

#define LDSM_X4(r0, r1, r2, r3, a) \
    asm volatile("ldmatrix.sync.aligned.m8n8.x4.shared.b16 {%0,%1,%2,%3}, [%4];" \
        : "=r"(r0), "=r"(r1), "=r"(r2), "=r"(r3) : "r"(a))

__device__ __forceinline__ void mma_f16(float* d, const uint32_t* a, const uint32_t* b) {
    asm volatile("mma.sync.aligned.m16n8k16.row.col.f32.f16.f16.f32 "
                 "{%0,%1,%2,%3}, {%4,%5,%6,%7}, {%8,%9}, {%0,%1,%2,%3};"
                 : "+f"(d[0]), "+f"(d[1]), "+f"(d[2]), "+f"(d[3])
                 : "r"(a[0]), "r"(a[1]), "r"(a[2]), "r"(a[3]),
                   "r"(b[0]), "r"(b[1]));
}

// ---- pack P,Q into fragment order ----
// block (g,ks,wn,j), lane l: n-col c = wn*32+j*8+(l>>2) -> k = g*4 + (c>>4), r = c&15
// d0 = ks*16 + 2*(l&3); halfs: P(d0),P(d0+1),P(d0+8),P(d0+9),Q(...)
__global__ void pack_b(const float* __restrict__ P, const float* __restrict__ Q) {
    int t = blockIdx.x * 256 + threadIdx.x;   // 0..32767
    int l = t & 31, j = (t >> 5) & 3, wn = (t >> 7) & 1, ks = (t >> 8) & 7, g = t >> 11;
    int c = wn * 32 + j * 8 + (l >> 2);
    int k = g * 4 + (c >> 4), r = c & 15;
    int d0 = ks * 16 + 2 * (l & 3);
    __half h[8];
    h[0] = __float2half_rn(P[(k * 128 + d0) * 16 + r]);
    h[1] = __float2half_rn(P[(k * 128 + d0 + 1) * 16 + r]);
    h[2] = __float2half_rn(P[(k * 128 + d0 + 8) * 16 + r]);
    h[3] = __float2half_rn(P[(k * 128 + d0 + 9) * 16 + r]);
    h[4] = __float2half_rn(Q[(k * 128 + d0) * 16 + r]);
    h[5] = __float2half_rn(Q[(k * 128 + d0 + 1) * 16 + r]);
    h[6] = __float2half_rn(Q[(k * 128 + d0 + 8) * 16 + r]);
    h[7] = __float2half_rn(Q[(k * 128 + d0 + 9) * 16 + r]);
    *reinterpret_cast<uint4*>(&g_B[t * 8]) = *reinterpret_cast<uint4*>(h);
}

// ---- pack W: block (ks,wn,tile), lane l: n = l>>2, k = 16*tile + 4*(n>>1) + 2*wn + (n&1)
__global__ void pack_w(const float* __restrict__ W) {
    int t = blockIdx.x * 256 + threadIdx.x;   // 0..2047
    int l = t & 31, tile = (t >> 5) & 3, wn = (t >> 7) & 1, ks = t >> 8;
    int n = l >> 2;
    int k = 16 * tile + 4 * (n >> 1) + 2 * wn + (n & 1);
    int d0 = ks * 16 + 2 * (l & 3);
    __half h[4];
    h[0] = __float2half_rn(W[k * 128 + d0]);
    h[1] = __float2half_rn(W[k * 128 + d0 + 1]);
    h[2] = __float2half_rn(W[k * 128 + d0 + 8]);
    h[3] = __float2half_rn(W[k * 128 + d0 + 9]);
    *reinterpret_cast<uint2*>(&g_Wt[t * 4]) = *reinterpret_cast<uint2*>(h);
}

// ---------------- main kernel ----------------
__global__ __launch_bounds__(THREADS, 2)
void antisym_h(const float* __restrict__ x1, const float* __restrict__ x2,
               float* __restrict__ out)
{
    extern __shared__ char shm[];
    const uint32_t smb = smem_u32(shm);
    const int tid = threadIdx.x;
    const int lane = tid & 31;
    const int wid = tid >> 5;
    const int wm = wid & 1;        // M-warp 0..1 (64 tokens each)
    const int wn = wid >> 1;       // N-warp 0..1
    const int g4 = lane >> 2;
    const int c4 = lane & 3;
    const int mbase = blockIdx.x * MTILE;

    // ---- stage z,s as fp16 (swizzled 256B rows), once ----
    {
        const float4* x1v = reinterpret_cast<const float4*>(x1) + (size_t)mbase * 32;
        const float4* x2v = reinterpret_cast<const float4*>(x2) + (size_t)mbase * 32;
        #pragma unroll
        for (int it = 0; it < 16; it++) {
            int idx = it * THREADS + tid;            // 2048 chunks
            int m = idx >> 4, c = idx & 15;
            float4 a0 = x1v[m * 32 + c * 2];
            float4 a1 = x1v[m * 32 + c * 2 + 1];
            float4 b0 = x2v[m * 32 + c * 2];
            float4 b1 = x2v[m * 32 + c * 2 + 1];
            half2 zz[4], ss[4];
            zz[0] = __floats2half2_rn(a0.x - b0.x, a0.y - b0.y);
            zz[1] = __floats2half2_rn(a0.z - b0.z, a0.w - b0.w);
            zz[2] = __floats2half2_rn(a1.x - b1.x, a1.y - b1.y);
            zz[3] = __floats2half2_rn(a1.z - b1.z, a1.w - b1.w);
            ss[0] = __floats2half2_rn(a0.x + b0.x, a0.y + b0.y);
            ss[1] = __floats2half2_rn(a0.z + b0.z, a0.w + b0.w);
            ss[2] = __floats2half2_rn(a1.x + b1.x, a1.y + b1.y);
            ss[3] = __floats2half2_rn(a1.z + b1.z, a1.w + b1.w);
            uint32_t so = (uint32_t)(m * 256 + ((c ^ (m & 7)) << 4));
            *reinterpret_cast<uint4*>(shm + ZSH + so) = *reinterpret_cast<uint4*>(zz);
            *reinterpret_cast<uint4*>(shm + SSH + so) = *reinterpret_cast<uint4*>(ss);
        }
    }
    __syncthreads();   // the ONLY barrier

    // ---- per-lane A ldmatrix row bases ----
    const int xr = lane & 7;
    uint32_t rowA[4];
    #pragma unroll
    for (int mi = 0; mi < 4; mi++)
        rowA[mi] = (uint32_t)((wm * 64 + mi * 16 + ((lane >> 3) & 1) * 8 + xr) * 256);
    const int krelA = lane >> 4;

    const uint4* bv = reinterpret_cast<const uint4*>(g_B);
    const uint2* wv = reinterpret_cast<const uint2*>(g_Wt);

    // ---- Phase L: lin = z @ W^T (per-warp packed W), store to out ----
    {
        float lw[4][4][4] = {};
        #pragma unroll
        for (int ks = 0; ks < 8; ks++) {
            uint32_t offA = (uint32_t)(((2 * ks + krelA) ^ xr) << 4);
            uint32_t az[4][4];
            #pragma unroll
            for (int mi = 0; mi < 4; mi++)
                LDSM_X4(az[mi][0], az[mi][1], az[mi][2], az[mi][3],
                        smb + ZSH + rowA[mi] + offA);
            #pragma unroll
            for (int t = 0; t < 4; t++) {
                uint2 w = wv[((ks * 2 + wn) * 4 + t) * 32 + lane];
                uint32_t bw[2] = {w.x, w.y};
                #pragma unroll
                for (int mi = 0; mi < 4; mi++)
                    mma_f16(lw[mi][t], az[mi], bw);
            }
        }
        #pragma unroll
        for (int mi = 0; mi < 4; mi++) {
            int m0 = mbase + wm * 64 + mi * 16 + g4;
            #pragma unroll
            for (int t = 0; t < 4; t++) {
                int k0 = 16 * t + 4 * c4 + 2 * wn;
                *reinterpret_cast<float2*>(&out[(size_t)m0 * KTOT + k0]) =
                    make_float2(lw[mi][t][0], lw[mi][t][1]);
                *reinterpret_cast<float2*>(&out[(size_t)(m0 + 8) * KTOT + k0]) =
                    make_float2(lw[mi][t][2], lw[mi][t][3]);
            }
        }
    }

    // ---- main loop: no barriers, B straight from L2 ----
    for (int g = 0; g < NGRP; g++) {
        float zp[4][4][4] = {};
        float sq[4][4][4] = {};

        #pragma unroll
        for (int ks = 0; ks < 8; ks++) {
            // B fragments: 4 LDG.128, coalesced, L2-hot
            uint4 v[4];
            const int bb = ((g * 8 + ks) * 2 + wn) * 4;
            #pragma unroll
            for (int j = 0; j < 4; j++) v[j] = bv[(bb + j) * 32 + lane];

            uint32_t offA = (uint32_t)(((2 * ks + krelA) ^ xr) << 4);
            uint32_t az[4][4], as_[4][4];
            #pragma unroll
            for (int mi = 0; mi < 4; mi++) {
                LDSM_X4(az[mi][0], az[mi][1], az[mi][2], az[mi][3],
                        smb + ZSH + rowA[mi] + offA);
                LDSM_X4(as_[mi][0], as_[mi][1], as_[mi][2], as_[mi][3],
                        smb + SSH + rowA[mi] + offA);
            }
            #pragma unroll
            for (int j = 0; j < 4; j++) {
                uint32_t bp[2] = {v[j].x, v[j].y};
                uint32_t bq[2] = {v[j].z, v[j].w};
                #pragma unroll
                for (int mi = 0; mi < 4; mi++) {
                    mma_f16(zp[mi][j], az[mi], bp);
                    mma_f16(sq[mi][j], as_[mi], bq);
                }
            }
        }

        // ---- epilogue: reduce r, RMW out (same lane wrote lin -> no fence) ----
        const int kA = g * 4 + 2 * wn;
        const bool writer = (c4 == (g & 3));
        #pragma unroll
        for (int mi = 0; mi < 4; mi++) {
            float pa0 = zp[mi][0][0]*sq[mi][0][0] + zp[mi][0][1]*sq[mi][0][1]
                      + zp[mi][1][0]*sq[mi][1][0] + zp[mi][1][1]*sq[mi][1][1];
            float pa1 = zp[mi][0][2]*sq[mi][0][2] + zp[mi][0][3]*sq[mi][0][3]
                      + zp[mi][1][2]*sq[mi][1][2] + zp[mi][1][3]*sq[mi][1][3];
            float pb0 = zp[mi][2][0]*sq[mi][2][0] + zp[mi][2][1]*sq[mi][2][1]
                      + zp[mi][3][0]*sq[mi][3][0] + zp[mi][3][1]*sq[mi][3][1];
            float pb1 = zp[mi][2][2]*sq[mi][2][2] + zp[mi][2][3]*sq[mi][2][3]
                      + zp[mi][3][2]*sq[mi][3][2] + zp[mi][3][3]*sq[mi][3][3];
            pa0 += __shfl_xor_sync(~0u, pa0, 1); pa0 += __shfl_xor_sync(~0u, pa0, 2);
            pa1 += __shfl_xor_sync(~0u, pa1, 1); pa1 += __shfl_xor_sync(~0u, pa1, 2);
            pb0 += __shfl_xor_sync(~0u, pb0, 1); pb0 += __shfl_xor_sync(~0u, pb0, 2);
            pb1 += __shfl_xor_sync(~0u, pb1, 1); pb1 += __shfl_xor_sync(~0u, pb1, 2);
            if (writer) {
                int m0 = mbase + wm * 64 + mi * 16 + g4;
                float2 l0 = *reinterpret_cast<const float2*>(&out[(size_t)m0 * KTOT + kA]);
                float2 l1 = *reinterpret_cast<const float2*>(&out[(size_t)(m0 + 8) * KTOT + kA]);
                *reinterpret_cast<float2*>(&out[(size_t)m0 * KTOT + kA]) =
                    make_float2(l0.x + pa0, l0.y + pb0);
                *reinterpret_cast<float2*>(&out[(size_t)(m0 + 8) * KTOT + kA]) =
                    make_float2(l1.x + pa1, l1.y + pb1);
            }
        }
    }
}

extern "C" void kernel_launch(void* const* d_in, const int* in_sizes, int n_in,
                              void* d_out, int out_size)
{
    const float* x1 = (const float*)d_in[0];
    const float* x2 = (const float*)d_in[1];
    const float* W  = (const float*)d_in[2];
    const float* P  = (const float*)d_in[3];
    const float* Q  = (const float*)d_in[4];
    float* out = (float*)d_out;

    pack_b<<<128, 256>>>(P, Q);
    pack_w<<<8, 256>>>(W);

    const int tokens = in_sizes[0] / D128;
    const int blocks = tokens / MTILE;      // 1024

    cudaFuncSetAttribute(antisym_h,
                         cudaFuncAttributeMaxDynamicSharedMemorySize, SMEM_BYTES);
    antisym_h<<<blocks, THREADS, SMEM_BYTES>>>(x1, x2, out);
}